// round 9
// baseline (speedup 1.0000x reference)
#include <cuda_runtime.h>
#include <cuda_bf16.h>

// GCN 2-layer: N=50000 nodes, E=800000 edges, feats 128 -> 64 -> 32.
//   h1 = x @ W1                        (raw, no scaling)
//   A[d] = dinv[d]*h1[d] + sum_{e:dst=d} dinv[src]*h1[src]
//   x1 = relu(dinv * A + b1)
//   g2 = dinv * (x1 @ W2)
//   out[d] = relu(dinv[d] * (g2[d] + sum g2[src]) + b2)
// R8: one-pass bucket CSR (cap 64), 7 kernels total, float2 gathers.

#define NMAX 50000
#define CAP  64
#define F1   64
#define F2   32

__device__ __align__(16) float d_dinv[NMAX];
__device__ __align__(16) float d_g1  [NMAX * F1];   // raw h1
__device__ __align__(16) float d_acc1[NMAX * F1];
__device__ __align__(16) float d_g2  [NMAX * F2];
__device__ int d_cnt[NMAX];           // in-degree (excl self loop)
__device__ int d_bkt[NMAX * CAP];     // src ids per dst
__device__ int d_is64;

// ---------------------------------------------------------------------------
__device__ __forceinline__ int edge_at(const void* ei, long long i, int n) {
    int v = d_is64 ? (int)((const long long*)ei)[i] : ((const int*)ei)[i];
    return min(max(v, 0), n - 1);   // defensive clamp
}

// init: zero cnt; thread 0 sniffs edge dtype (int64 has zero high halves).
__global__ void init_kernel(const void* ei, int n) {
    int i = blockIdx.x * blockDim.x + threadIdx.x;
    if (i < n) d_cnt[i] = 0;
    if (i == 0) {
        const unsigned* w = (const unsigned*)ei;
        int all_zero = 1;
        for (int k = 0; k < 64; k++)
            if (w[2 * k + 1] != 0u) { all_zero = 0; break; }
        d_is64 = all_zero;
    }
}

// one-pass CSR build: count + bucket fill.
__global__ void fill_kernel(const void* __restrict__ ei, int E, int n) {
    int e = blockIdx.x * blockDim.x + threadIdx.x;
    if (e < E) {
        int s = edge_at(ei, e, n);
        int d = edge_at(ei, (long long)E + e, n);
        int slot = atomicAdd(&d_cnt[d], 1);
        if (slot < CAP) d_bkt[d * CAP + slot] = s;
    }
}

__global__ void dinv_kernel(int n) {
    int i = blockIdx.x * blockDim.x + threadIdx.x;
    if (i < n) d_dinv[i] = rsqrtf(1.0f + (float)d_cnt[i]);
}

// ---------------------------------------------------------------------------
// GEMM1 (raw): h1[i][j] = sum_k x[i][k] * W1[k][j]   (K=128, COLS=64)
__global__ __launch_bounds__(256) void gemm1_kernel(
    const float* __restrict__ x, const float* __restrict__ W, int n)
{
    __shared__ __align__(16) float Ws[128][64];   // 32 KB
    __shared__ __align__(16) float Xs[32][128];   // 16 KB
    const int t = threadIdx.x;
    const int row0 = blockIdx.x * 32;

    for (int i = t; i < 128 * 64; i += 256) Ws[i >> 6][i & 63] = W[i];
    for (int i = t; i < 32 * 128; i += 256) {
        int r = i >> 7, k = i & 127;
        int row = row0 + r;
        Xs[r][k] = (row < n) ? x[(size_t)row * 128 + k] : 0.0f;
    }
    __syncthreads();

    const int col = (t & 15) * 4;
    const int rg  = t >> 4;
    float4 a0 = {0.f, 0.f, 0.f, 0.f};
    float4 a1 = {0.f, 0.f, 0.f, 0.f};

    #pragma unroll 8
    for (int k = 0; k < 128; k++) {
        float4 w = *(const float4*)&Ws[k][col];
        float x0 = Xs[rg * 2 + 0][k];
        float x1 = Xs[rg * 2 + 1][k];
        a0.x += x0 * w.x; a0.y += x0 * w.y; a0.z += x0 * w.z; a0.w += x0 * w.w;
        a1.x += x1 * w.x; a1.y += x1 * w.y; a1.z += x1 * w.z; a1.w += x1 * w.w;
    }

    int row = row0 + rg * 2;
    if (row < n)     *(float4*)&d_g1[(size_t)row * F1 + col] = a0;
    row++;
    if (row < n)     *(float4*)&d_g1[(size_t)row * F1 + col] = a1;
}

// ---------------------------------------------------------------------------
// Gather1: one warp per dst; lane holds float2 (32*8B = full 256B row).
//   acc1[d] = dinv[d]*h1[d] + sum dinv[s]*h1[s]
__global__ __launch_bounds__(256) void gather1_kernel(int n)
{
    int w    = (blockIdx.x * blockDim.x + threadIdx.x) >> 5;
    int lane = threadIdx.x & 31;
    if (w >= n) return;
    int m = min(d_cnt[w], CAP);
    float dw = d_dinv[w];
    float2 a = ((const float2*)(d_g1 + (size_t)w * F1))[lane];
    a.x *= dw; a.y *= dw;                      // self loop
    const int* bp = d_bkt + w * CAP;
    int j = 0;
    for (; j + 1 < m; j += 2) {
        int s0 = bp[j], s1 = bp[j + 1];
        float e0 = d_dinv[s0], e1 = d_dinv[s1];
        float2 v0 = ((const float2*)(d_g1 + (size_t)s0 * F1))[lane];
        float2 v1 = ((const float2*)(d_g1 + (size_t)s1 * F1))[lane];
        a.x += e0 * v0.x; a.y += e0 * v0.y;
        a.x += e1 * v1.x; a.y += e1 * v1.y;
    }
    if (j < m) {
        int s = bp[j];
        float e = d_dinv[s];
        float2 v = ((const float2*)(d_g1 + (size_t)s * F1))[lane];
        a.x += e * v.x; a.y += e * v.y;
    }
    ((float2*)(d_acc1 + (size_t)w * F1))[lane] = a;
}

// ---------------------------------------------------------------------------
// GEMM2: x1[i][k] = relu(acc1[i][k]*dinv[i] + b1[k]);
//        g2[i][j] = dinv[i] * sum_k x1[i][k] * W2[k][j]   (K=64, COLS=32)
__global__ __launch_bounds__(256) void gemm2_kernel(
    const float* __restrict__ W, const float* __restrict__ b1, int n)
{
    __shared__ __align__(16) float Ws[64][32];    // 8 KB
    __shared__ __align__(16) float Xs[64][64];    // 16 KB
    const int t = threadIdx.x;
    const int row0 = blockIdx.x * 64;

    for (int i = t; i < 64 * 32; i += 256) Ws[i >> 5][i & 31] = W[i];
    for (int i = t; i < 64 * 64; i += 256) {
        int r = i >> 6, k = i & 63;
        int row = row0 + r;
        float v = 0.0f;
        if (row < n)
            v = fmaxf(d_acc1[(size_t)row * F1 + k] * d_dinv[row] + b1[k], 0.0f);
        Xs[r][k] = v;
    }
    __syncthreads();

    const int col = (t & 7) * 4;
    const int rg  = t >> 3;
    float4 a0 = {0.f, 0.f, 0.f, 0.f};
    float4 a1 = {0.f, 0.f, 0.f, 0.f};

    #pragma unroll 8
    for (int k = 0; k < 64; k++) {
        float4 w = *(const float4*)&Ws[k][col];
        float x0 = Xs[rg * 2 + 0][k];
        float x1 = Xs[rg * 2 + 1][k];
        a0.x += x0 * w.x; a0.y += x0 * w.y; a0.z += x0 * w.z; a0.w += x0 * w.w;
        a1.x += x1 * w.x; a1.y += x1 * w.y; a1.z += x1 * w.z; a1.w += x1 * w.w;
    }

    int row = row0 + rg * 2;
    #pragma unroll
    for (int rr = 0; rr < 2; rr++, row++) {
        if (row < n) {
            float s = d_dinv[row];
            float4 a = (rr == 0) ? a0 : a1;
            float4 o = {a.x * s, a.y * s, a.z * s, a.w * s};
            *(float4*)&d_g2[(size_t)row * F2 + col] = o;
        }
    }
}

// ---------------------------------------------------------------------------
// Gather2 + epilogue: out[d] = relu(dinv[d]*(g2[d] + sum g2[src]) + b2)
// (g2 already carries the dinv[src] factor from gemm2's epilogue.)
__global__ __launch_bounds__(256) void gather2_kernel(
    const float* __restrict__ b2, float* __restrict__ out, int n)
{
    int w    = (blockIdx.x * blockDim.x + threadIdx.x) >> 5;
    int lane = threadIdx.x & 31;
    if (w >= n) return;
    int m = min(d_cnt[w], CAP);
    float a = d_g2[(size_t)w * F2 + lane];         // self loop
    const int* bp = d_bkt + w * CAP;
    int j = 0;
    for (; j + 3 < m; j += 4) {
        int s0 = bp[j], s1 = bp[j + 1], s2 = bp[j + 2], s3 = bp[j + 3];
        float v0 = d_g2[(size_t)s0 * F2 + lane];
        float v1 = d_g2[(size_t)s1 * F2 + lane];
        float v2 = d_g2[(size_t)s2 * F2 + lane];
        float v3 = d_g2[(size_t)s3 * F2 + lane];
        a += v0; a += v1; a += v2; a += v3;
    }
    for (; j < m; j++)
        a += d_g2[(size_t)bp[j] * F2 + lane];
    out[(size_t)w * F2 + lane] = fmaxf(a * d_dinv[w] + b2[lane], 0.0f);
}

// ---------------------------------------------------------------------------
extern "C" void kernel_launch(void* const* d_in, const int* in_sizes, int n_in,
                              void* d_out, int out_size)
{
    const float* x  = (const float*)d_in[0];   // [N,128]
    const void*  ei = d_in[1];                 // [2,E], int32 or int64
    const float* W1 = (const float*)d_in[2];   // [128,64]
    const float* b1 = (const float*)d_in[3];   // [64]
    const float* W2 = (const float*)d_in[4];   // [64,32]
    const float* b2 = (const float*)d_in[5];   // [32]
    float*       out = (float*)d_out;

    const int N = in_sizes[0] / 128;
    const int E = in_sizes[1] / 2;

    // CSR build chain (one edge pass) + dinv
    init_kernel<<<(N + 255) / 256, 256>>>(ei, N);
    fill_kernel<<<(E + 255) / 256, 256>>>(ei, E, N);
    dinv_kernel<<<(N + 255) / 256, 256>>>(N);

    // layer 1
    gemm1_kernel<<<(N + 31) / 32, 256>>>(x, W1, N);
    gather1_kernel<<<(N + 7) / 8, 256>>>(N);

    // layer 2
    gemm2_kernel<<<(N + 63) / 64, 256>>>(W2, b1, N);
    gather2_kernel<<<(N + 7) / 8, 256>>>(b2, out, N);
}

// round 10
// speedup vs baseline: 1.6384x; 1.6384x over previous
#include <cuda_runtime.h>
#include <cuda_bf16.h>

// GCN 2-layer: N=50000 nodes, E=800000 edges, feats 128 -> 64 -> 32.
//   g1 = dinv ⊙ (x @ W1)
//   acc1[d] = g1[d] + sum_{e:dst=d} g1[src]
//   x1 = relu(dinv ⊙ acc1 + b1)
//   g2 = dinv ⊙ (x1 @ W2)
//   out[d] = relu(dinv[d] * (g2[d] + sum g2[src]) + b2)
// R9: gemm1 rebuilt as 64x64-tile / 4x4-per-thread SGEMM with packed
// fma.rn.f32x2 (FFMA2); gather1 reverted to dependent-load-free form.

#define NMAX 50000
#define CAP  64
#define F1   64
#define F2   32

__device__ __align__(16) float d_dinv[NMAX];
__device__ __align__(16) float d_g1  [NMAX * F1];
__device__ __align__(16) float d_acc1[NMAX * F1];
__device__ __align__(16) float d_g2  [NMAX * F2];
__device__ int d_cnt[NMAX];           // in-degree (excl self loop)
__device__ int d_bkt[NMAX * CAP];     // src ids per dst
__device__ int d_is64;

// ---------------------------------------------------------------------------
__device__ __forceinline__ int edge_at(const void* ei, long long i, int n) {
    int v = d_is64 ? (int)((const long long*)ei)[i] : ((const int*)ei)[i];
    return min(max(v, 0), n - 1);   // defensive clamp
}

// init: zero cnt; thread 0 sniffs edge dtype (int64 has zero high halves).
__global__ void init_kernel(const void* ei, int n) {
    int i = blockIdx.x * blockDim.x + threadIdx.x;
    if (i < n) d_cnt[i] = 0;
    if (i == 0) {
        const unsigned* w = (const unsigned*)ei;
        int all_zero = 1;
        for (int k = 0; k < 64; k++)
            if (w[2 * k + 1] != 0u) { all_zero = 0; break; }
        d_is64 = all_zero;
    }
}

// one-pass CSR build: count + bucket fill.
__global__ void fill_kernel(const void* __restrict__ ei, int E, int n) {
    int e = blockIdx.x * blockDim.x + threadIdx.x;
    if (e < E) {
        int s = edge_at(ei, e, n);
        int d = edge_at(ei, (long long)E + e, n);
        int slot = atomicAdd(&d_cnt[d], 1);
        if (slot < CAP) d_bkt[d * CAP + slot] = s;
    }
}

__global__ void dinv_kernel(int n) {
    int i = blockIdx.x * blockDim.x + threadIdx.x;
    if (i < n) d_dinv[i] = rsqrtf(1.0f + (float)d_cnt[i]);
}

// ---------------------------------------------------------------------------
// Packed fp32x2 FMA helpers (sm_103a FFMA2).
__device__ __forceinline__ unsigned long long pack2(float lo, float hi) {
    unsigned long long r;
    asm("mov.b64 %0, {%1, %2};" : "=l"(r) : "f"(lo), "f"(hi));
    return r;
}
__device__ __forceinline__ void fma2(unsigned long long& acc,
                                     unsigned long long a, unsigned long long b) {
    asm("fma.rn.f32x2 %0, %1, %2, %0;" : "+l"(acc) : "l"(a), "l"(b));
}
__device__ __forceinline__ void unpack2(unsigned long long v, float& lo, float& hi) {
    asm("mov.b64 {%0, %1}, %2;" : "=f"(lo), "=f"(hi) : "l"(v));
}

// ---------------------------------------------------------------------------
// GEMM1: g1[i][j] = dinv[i] * sum_k x[i][k] * W1[k][j]   (K=128, COLS=64)
// 64x64 tile, K in 2 chunks of 64. X stored k-major (transposed, padded).
// 256 threads, each computes 4 rows x 4 cols via 8 FFMA2 per k.
__global__ __launch_bounds__(256) void gemm1_kernel(
    const float* __restrict__ x, const float* __restrict__ W, int n)
{
    __shared__ float Xt[64][65];                 // [k][row], padded
    __shared__ __align__(16) float Ws[64][64];   // [k][col]
    const int t = threadIdx.x;
    const int row0 = blockIdx.x * 64;
    const int tc = (t & 15) * 4;                 // col group
    const int tr = (t >> 4) * 4;                 // row group

    unsigned long long acc[4][2] = {};           // 4 rows x (2 packed col-pairs)

    for (int kc = 0; kc < 128; kc += 64) {
        __syncthreads();
        for (int i = t; i < 4096; i += 256) {    // W chunk [64k][64c]
            int k = i >> 6, c = i & 63;
            Ws[k][c] = W[(size_t)(kc + k) * 64 + c];
        }
        for (int i = t; i < 4096; i += 256) {    // X chunk transposed
            int r = i >> 6, k = i & 63;
            int row = row0 + r;
            Xt[k][r] = (row < n) ? x[(size_t)row * 128 + kc + k] : 0.0f;
        }
        __syncthreads();

        #pragma unroll 8
        for (int k = 0; k < 64; k++) {
            float4 w = *(const float4*)&Ws[k][tc];
            unsigned long long w01 = pack2(w.x, w.y);
            unsigned long long w23 = pack2(w.z, w.w);
            #pragma unroll
            for (int r = 0; r < 4; r++) {
                float xr = Xt[k][tr + r];
                unsigned long long xx = pack2(xr, xr);
                fma2(acc[r][0], xx, w01);
                fma2(acc[r][1], xx, w23);
            }
        }
    }

    #pragma unroll
    for (int r = 0; r < 4; r++) {
        int row = row0 + tr + r;
        if (row < n) {
            float s = d_dinv[row];
            float o0, o1, o2, o3;
            unpack2(acc[r][0], o0, o1);
            unpack2(acc[r][1], o2, o3);
            float4 o = {o0 * s, o1 * s, o2 * s, o3 * s};
            *(float4*)&d_g1[(size_t)row * F1 + tc] = o;
        }
    }
}

// ---------------------------------------------------------------------------
// Gather1: one warp per dst; lane holds float2 (32*8B = full 256B row).
//   acc1[d] = g1[d] + sum g1[src]        (no per-edge scalar loads)
__global__ __launch_bounds__(256) void gather1_kernel(int n)
{
    int w    = (blockIdx.x * blockDim.x + threadIdx.x) >> 5;
    int lane = threadIdx.x & 31;
    if (w >= n) return;
    int m = min(d_cnt[w], CAP);
    float2 a = ((const float2*)(d_g1 + (size_t)w * F1))[lane];   // self loop
    const int* bp = d_bkt + w * CAP;
    int j = 0;
    for (; j + 1 < m; j += 2) {
        int s0 = bp[j], s1 = bp[j + 1];
        float2 v0 = ((const float2*)(d_g1 + (size_t)s0 * F1))[lane];
        float2 v1 = ((const float2*)(d_g1 + (size_t)s1 * F1))[lane];
        a.x += v0.x; a.y += v0.y;
        a.x += v1.x; a.y += v1.y;
    }
    if (j < m) {
        float2 v = ((const float2*)(d_g1 + (size_t)bp[j] * F1))[lane];
        a.x += v.x; a.y += v.y;
    }
    ((float2*)(d_acc1 + (size_t)w * F1))[lane] = a;
}

// ---------------------------------------------------------------------------
// GEMM2: x1[i][k] = relu(acc1[i][k]*dinv[i] + b1[k]);
//        g2[i][j] = dinv[i] * sum_k x1[i][k] * W2[k][j]   (K=64, COLS=32)
__global__ __launch_bounds__(256) void gemm2_kernel(
    const float* __restrict__ W, const float* __restrict__ b1, int n)
{
    __shared__ __align__(16) float Ws[64][32];    // 8 KB
    __shared__ __align__(16) float Xs[64][64];    // 16 KB
    const int t = threadIdx.x;
    const int row0 = blockIdx.x * 64;

    for (int i = t; i < 64 * 32; i += 256) Ws[i >> 5][i & 31] = W[i];
    for (int i = t; i < 64 * 64; i += 256) {
        int r = i >> 6, k = i & 63;
        int row = row0 + r;
        float v = 0.0f;
        if (row < n)
            v = fmaxf(d_acc1[(size_t)row * F1 + k] * d_dinv[row] + b1[k], 0.0f);
        Xs[r][k] = v;
    }
    __syncthreads();

    const int col = (t & 7) * 4;
    const int rg  = t >> 3;
    float4 a0 = {0.f, 0.f, 0.f, 0.f};
    float4 a1 = {0.f, 0.f, 0.f, 0.f};

    #pragma unroll 8
    for (int k = 0; k < 64; k++) {
        float4 w = *(const float4*)&Ws[k][col];
        float x0 = Xs[rg * 2 + 0][k];
        float x1 = Xs[rg * 2 + 1][k];
        a0.x += x0 * w.x; a0.y += x0 * w.y; a0.z += x0 * w.z; a0.w += x0 * w.w;
        a1.x += x1 * w.x; a1.y += x1 * w.y; a1.z += x1 * w.z; a1.w += x1 * w.w;
    }

    int row = row0 + rg * 2;
    #pragma unroll
    for (int rr = 0; rr < 2; rr++, row++) {
        if (row < n) {
            float s = d_dinv[row];
            float4 a = (rr == 0) ? a0 : a1;
            float4 o = {a.x * s, a.y * s, a.z * s, a.w * s};
            *(float4*)&d_g2[(size_t)row * F2 + col] = o;
        }
    }
}

// ---------------------------------------------------------------------------
// Gather2 + epilogue: out[d] = relu(dinv[d]*(g2[d] + sum g2[src]) + b2)
__global__ __launch_bounds__(256) void gather2_kernel(
    const float* __restrict__ b2, float* __restrict__ out, int n)
{
    int w    = (blockIdx.x * blockDim.x + threadIdx.x) >> 5;
    int lane = threadIdx.x & 31;
    if (w >= n) return;
    int m = min(d_cnt[w], CAP);
    float a = d_g2[(size_t)w * F2 + lane];         // self loop
    const int* bp = d_bkt + w * CAP;
    int j = 0;
    for (; j + 3 < m; j += 4) {
        int s0 = bp[j], s1 = bp[j + 1], s2 = bp[j + 2], s3 = bp[j + 3];
        float v0 = d_g2[(size_t)s0 * F2 + lane];
        float v1 = d_g2[(size_t)s1 * F2 + lane];
        float v2 = d_g2[(size_t)s2 * F2 + lane];
        float v3 = d_g2[(size_t)s3 * F2 + lane];
        a += v0; a += v1; a += v2; a += v3;
    }
    for (; j < m; j++)
        a += d_g2[(size_t)bp[j] * F2 + lane];
    out[(size_t)w * F2 + lane] = fmaxf(a * d_dinv[w] + b2[lane], 0.0f);
}

// ---------------------------------------------------------------------------
extern "C" void kernel_launch(void* const* d_in, const int* in_sizes, int n_in,
                              void* d_out, int out_size)
{
    const float* x  = (const float*)d_in[0];   // [N,128]
    const void*  ei = d_in[1];                 // [2,E], int32 or int64
    const float* W1 = (const float*)d_in[2];   // [128,64]
    const float* b1 = (const float*)d_in[3];   // [64]
    const float* W2 = (const float*)d_in[4];   // [64,32]
    const float* b2 = (const float*)d_in[5];   // [32]
    float*       out = (float*)d_out;

    const int N = in_sizes[0] / 128;
    const int E = in_sizes[1] / 2;

    // CSR build chain (one edge pass) + dinv
    init_kernel<<<(N + 255) / 256, 256>>>(ei, N);
    fill_kernel<<<(E + 255) / 256, 256>>>(ei, E, N);
    dinv_kernel<<<(N + 255) / 256, 256>>>(N);

    // layer 1
    gemm1_kernel<<<(N + 63) / 64, 256>>>(x, W1, N);
    gather1_kernel<<<(N + 7) / 8, 256>>>(N);

    // layer 2
    gemm2_kernel<<<(N + 63) / 64, 256>>>(W2, b1, N);
    gather2_kernel<<<(N + 7) / 8, 256>>>(b2, out, N);
}

// round 11
// speedup vs baseline: 1.6389x; 1.0003x over previous
#include <cuda_runtime.h>
#include <cuda_bf16.h>

// GCN 2-layer: N=50000 nodes, E=800000 edges, feats 128 -> 64 -> 32.
//   g1 = dinv ⊙ (x @ W1)
//   acc1[d] = g1[d] + sum_{e:dst=d} g1[src]
//   x1 = relu(dinv ⊙ acc1 + b1);  g2 = dinv ⊙ (x1 @ W2)
//   out[d] = relu(dinv[d] * (g2[d] + sum g2[src]) + b2)
// R10: packed CSR (scan-based, R7-proven) + 128x64-tile FFMA2 gemm1.

#define NMAX 50000
#define EMAX 800000
#define F1   64
#define F2   32
#define SCAN_B 512

__device__ __align__(16) float d_dinv[NMAX];
__device__ __align__(16) float d_g1  [NMAX * F1];
__device__ __align__(16) float d_acc1[NMAX * F1];
__device__ __align__(16) float d_g2  [NMAX * F2];
__device__ int d_cnt [NMAX];
__device__ int d_off [NMAX];
__device__ int d_cur [NMAX];
__device__ int d_csr [EMAX];
__device__ int d_bsum[(NMAX + SCAN_B - 1) / SCAN_B];
__device__ int d_is64;

// ---------------------------------------------------------------------------
__device__ __forceinline__ int edge_at(const void* ei, long long i, int n) {
    int v = d_is64 ? (int)((const long long*)ei)[i] : ((const int*)ei)[i];
    return min(max(v, 0), n - 1);
}

__global__ void init_kernel(const void* ei, int n) {
    int i = blockIdx.x * blockDim.x + threadIdx.x;
    if (i < n) d_cnt[i] = 0;
    if (i == 0) {
        const unsigned* w = (const unsigned*)ei;
        int all_zero = 1;
        for (int k = 0; k < 64; k++)
            if (w[2 * k + 1] != 0u) { all_zero = 0; break; }
        d_is64 = all_zero;
    }
}

__global__ void cnt_count_kernel(const void* __restrict__ ei, int E, int n) {
    int e = blockIdx.x * blockDim.x + threadIdx.x;
    if (e < E) atomicAdd(&d_cnt[edge_at(ei, (long long)E + e, n)], 1);
}

// Two-level exclusive scan of d_cnt -> d_off -------------------------------
__global__ __launch_bounds__(SCAN_B) void scan1_kernel(int n) {
    __shared__ int sh[SCAN_B];
    int i = blockIdx.x * SCAN_B + threadIdx.x;
    int v = (i < n) ? d_cnt[i] : 0;
    sh[threadIdx.x] = v;
    __syncthreads();
    #pragma unroll
    for (int ofs = 1; ofs < SCAN_B; ofs <<= 1) {
        int t = (threadIdx.x >= ofs) ? sh[threadIdx.x - ofs] : 0;
        __syncthreads();
        sh[threadIdx.x] += t;
        __syncthreads();
    }
    if (i < n) d_off[i] = sh[threadIdx.x] - v;
    if (threadIdx.x == SCAN_B - 1) d_bsum[blockIdx.x] = sh[SCAN_B - 1];
}

__global__ void scan2_kernel(int nb) {
    if (threadIdx.x == 0 && blockIdx.x == 0) {
        int acc = 0;
        for (int b = 0; b < nb; b++) { int t = d_bsum[b]; d_bsum[b] = acc; acc += t; }
    }
}

// scan3 + dinv fused
__global__ void scan3_kernel(int n) {
    int i = blockIdx.x * blockDim.x + threadIdx.x;
    if (i < n) {
        int o = d_off[i] + d_bsum[i / SCAN_B];
        d_off[i] = o;
        d_cur[i] = o;
        d_dinv[i] = rsqrtf(1.0f + (float)d_cnt[i]);
    }
}

__global__ void fill_kernel(const void* __restrict__ ei, int E, int n) {
    int e = blockIdx.x * blockDim.x + threadIdx.x;
    if (e < E) {
        int s = edge_at(ei, e, n);
        int d = edge_at(ei, (long long)E + e, n);
        d_csr[atomicAdd(&d_cur[d], 1)] = s;
    }
}

// ---------------------------------------------------------------------------
// Packed fp32x2 helpers (sm_103a FFMA2).
__device__ __forceinline__ unsigned long long pack2(float lo, float hi) {
    unsigned long long r;
    asm("mov.b64 %0, {%1, %2};" : "=l"(r) : "f"(lo), "f"(hi));
    return r;
}
__device__ __forceinline__ void fma2(unsigned long long& acc,
                                     unsigned long long a, unsigned long long b) {
    asm("fma.rn.f32x2 %0, %1, %2, %0;" : "+l"(acc) : "l"(a), "l"(b));
}
__device__ __forceinline__ void unpack2(unsigned long long v, float& lo, float& hi) {
    asm("mov.b64 {%0, %1}, %2;" : "=f"(lo), "=f"(hi) : "l"(v));
}

// ---------------------------------------------------------------------------
// GEMM1: g1[i][j] = dinv[i] * sum_k x[i][k] * W1[k][j]   (K=128, N=64)
// Tile 128 rows x 64 cols, 256 threads: each 8 rows x 4 cols.
// X staged transposed Xt[k][row] so row-pairs are free reg-pairs for FFMA2.
#define XPAD 132
__global__ __launch_bounds__(256) void gemm1_kernel(
    const float* __restrict__ x, const float* __restrict__ W, int n)
{
    __shared__ __align__(16) float Ws[32][64];     // 8 KB
    __shared__ __align__(16) float Xt[32][XPAD];   // 16.5 KB
    const int t = threadIdx.x;
    const int row0 = blockIdx.x * 128;
    const int cg = (t & 15) * 4;                   // 4 cols
    const int rg = (t >> 4) * 8;                   // 8 rows

    unsigned long long acc[4][4] = {};             // [col j][rowpair p]

    for (int kc = 0; kc < 128; kc += 32) {
        __syncthreads();
        #pragma unroll
        for (int i = 0; i < 2; i++) {              // W chunk: 512 float4
            int idx = t + 256 * i;
            int k = idx >> 4, c4 = (idx & 15) * 4;
            *(float4*)&Ws[k][c4] = *(const float4*)&W[(size_t)(kc + k) * 64 + c4];
        }
        #pragma unroll
        for (int i = 0; i < 4; i++) {              // X chunk transposed
            int idx = t + 256 * i;                 // 1024 float4 reads
            int r = idx >> 3, q = idx & 7;
            int row = row0 + r;
            float4 v = {0.f, 0.f, 0.f, 0.f};
            if (row < n)
                v = *(const float4*)&x[(size_t)row * 128 + kc + q * 4];
            Xt[q * 4 + 0][r] = v.x;
            Xt[q * 4 + 1][r] = v.y;
            Xt[q * 4 + 2][r] = v.z;
            Xt[q * 4 + 3][r] = v.w;
        }
        __syncthreads();

        #pragma unroll 4
        for (int k = 0; k < 32; k++) {
            float4 w = *(const float4*)&Ws[k][cg];
            unsigned long long wd0 = pack2(w.x, w.x);
            unsigned long long wd1 = pack2(w.y, w.y);
            unsigned long long wd2 = pack2(w.z, w.z);
            unsigned long long wd3 = pack2(w.w, w.w);
            float4 xa = *(const float4*)&Xt[k][rg];
            float4 xb = *(const float4*)&Xt[k][rg + 4];
            unsigned long long xp[4] = {
                pack2(xa.x, xa.y), pack2(xa.z, xa.w),
                pack2(xb.x, xb.y), pack2(xb.z, xb.w) };
            #pragma unroll
            for (int p = 0; p < 4; p++) {
                fma2(acc[0][p], xp[p], wd0);
                fma2(acc[1][p], xp[p], wd1);
                fma2(acc[2][p], xp[p], wd2);
                fma2(acc[3][p], xp[p], wd3);
            }
        }
    }

    #pragma unroll
    for (int p = 0; p < 4; p++) {
        float c0l, c0h, c1l, c1h, c2l, c2h, c3l, c3h;
        unpack2(acc[0][p], c0l, c0h);
        unpack2(acc[1][p], c1l, c1h);
        unpack2(acc[2][p], c2l, c2h);
        unpack2(acc[3][p], c3l, c3h);
        int row = row0 + rg + 2 * p;
        if (row < n) {
            float s = d_dinv[row];
            float4 o = {c0l * s, c1l * s, c2l * s, c3l * s};
            *(float4*)&d_g1[(size_t)row * F1 + cg] = o;
        }
        row++;
        if (row < n) {
            float s = d_dinv[row];
            float4 o = {c0h * s, c1h * s, c2h * s, c3h * s};
            *(float4*)&d_g1[(size_t)row * F1 + cg] = o;
        }
    }
}

// ---------------------------------------------------------------------------
// Gather1: one warp per dst; lane holds float2 (32*8B = 256B row).
__global__ __launch_bounds__(256) void gather1_kernel(int n)
{
    int w    = (blockIdx.x * blockDim.x + threadIdx.x) >> 5;
    int lane = threadIdx.x & 31;
    if (w >= n) return;
    int beg = d_off[w];
    int end = beg + d_cnt[w];
    float2 a = ((const float2*)(d_g1 + (size_t)w * F1))[lane];   // self loop
    int j = beg;
    for (; j + 1 < end; j += 2) {
        int s0 = d_csr[j], s1 = d_csr[j + 1];
        float2 v0 = ((const float2*)(d_g1 + (size_t)s0 * F1))[lane];
        float2 v1 = ((const float2*)(d_g1 + (size_t)s1 * F1))[lane];
        a.x += v0.x; a.y += v0.y;
        a.x += v1.x; a.y += v1.y;
    }
    if (j < end) {
        float2 v = ((const float2*)(d_g1 + (size_t)d_csr[j] * F1))[lane];
        a.x += v.x; a.y += v.y;
    }
    ((float2*)(d_acc1 + (size_t)w * F1))[lane] = a;
}

// ---------------------------------------------------------------------------
// GEMM2: x1[i][k] = relu(acc1[i][k]*dinv[i] + b1[k]);
//        g2[i][j] = dinv[i] * sum_k x1[i][k] * W2[k][j]   (K=64, N=32)
__global__ __launch_bounds__(256) void gemm2_kernel(
    const float* __restrict__ W, const float* __restrict__ b1, int n)
{
    __shared__ __align__(16) float Ws[64][32];
    __shared__ __align__(16) float Xs[64][64];
    const int t = threadIdx.x;
    const int row0 = blockIdx.x * 64;

    for (int i = t; i < 64 * 32; i += 256) Ws[i >> 5][i & 31] = W[i];
    for (int i = t; i < 64 * 64; i += 256) {
        int r = i >> 6, k = i & 63;
        int row = row0 + r;
        float v = 0.0f;
        if (row < n)
            v = fmaxf(d_acc1[(size_t)row * F1 + k] * d_dinv[row] + b1[k], 0.0f);
        Xs[r][k] = v;
    }
    __syncthreads();

    const int col = (t & 7) * 4;
    const int rg  = t >> 3;
    float4 a0 = {0.f, 0.f, 0.f, 0.f};
    float4 a1 = {0.f, 0.f, 0.f, 0.f};

    #pragma unroll 8
    for (int k = 0; k < 64; k++) {
        float4 w = *(const float4*)&Ws[k][col];
        float x0 = Xs[rg * 2 + 0][k];
        float x1 = Xs[rg * 2 + 1][k];
        a0.x += x0 * w.x; a0.y += x0 * w.y; a0.z += x0 * w.z; a0.w += x0 * w.w;
        a1.x += x1 * w.x; a1.y += x1 * w.y; a1.z += x1 * w.z; a1.w += x1 * w.w;
    }

    int row = row0 + rg * 2;
    #pragma unroll
    for (int rr = 0; rr < 2; rr++, row++) {
        if (row < n) {
            float s = d_dinv[row];
            float4 a = (rr == 0) ? a0 : a1;
            float4 o = {a.x * s, a.y * s, a.z * s, a.w * s};
            *(float4*)&d_g2[(size_t)row * F2 + col] = o;
        }
    }
}

// ---------------------------------------------------------------------------
// Gather2 + epilogue: out[d] = relu(dinv[d]*(g2[d] + sum g2[src]) + b2)
__global__ __launch_bounds__(256) void gather2_kernel(
    const float* __restrict__ b2, float* __restrict__ out, int n)
{
    int w    = (blockIdx.x * blockDim.x + threadIdx.x) >> 5;
    int lane = threadIdx.x & 31;
    if (w >= n) return;
    int beg = d_off[w];
    int end = beg + d_cnt[w];
    float a = d_g2[(size_t)w * F2 + lane];
    int j = beg;
    for (; j + 3 < end; j += 4) {
        int s0 = d_csr[j], s1 = d_csr[j + 1], s2 = d_csr[j + 2], s3 = d_csr[j + 3];
        float v0 = d_g2[(size_t)s0 * F2 + lane];
        float v1 = d_g2[(size_t)s1 * F2 + lane];
        float v2 = d_g2[(size_t)s2 * F2 + lane];
        float v3 = d_g2[(size_t)s3 * F2 + lane];
        a += v0; a += v1; a += v2; a += v3;
    }
    for (; j < end; j++)
        a += d_g2[(size_t)d_csr[j] * F2 + lane];
    out[(size_t)w * F2 + lane] = fmaxf(a * d_dinv[w] + b2[lane], 0.0f);
}

// ---------------------------------------------------------------------------
extern "C" void kernel_launch(void* const* d_in, const int* in_sizes, int n_in,
                              void* d_out, int out_size)
{
    const float* x  = (const float*)d_in[0];
    const void*  ei = d_in[1];
    const float* W1 = (const float*)d_in[2];
    const float* b1 = (const float*)d_in[3];
    const float* W2 = (const float*)d_in[4];
    const float* b2 = (const float*)d_in[5];
    float*       out = (float*)d_out;

    const int N = in_sizes[0] / 128;
    const int E = in_sizes[1] / 2;
    const int NB = (N + SCAN_B - 1) / SCAN_B;

    // CSR build (packed) + dinv
    init_kernel<<<(N + 255) / 256, 256>>>(ei, N);
    cnt_count_kernel<<<(E + 255) / 256, 256>>>(ei, E, N);
    scan1_kernel<<<NB, SCAN_B>>>(N);
    scan2_kernel<<<1, 32>>>(NB);
    scan3_kernel<<<(N + 255) / 256, 256>>>(N);
    fill_kernel<<<(E + 255) / 256, 256>>>(ei, E, N);

    // layer 1
    gemm1_kernel<<<(N + 127) / 128, 256>>>(x, W1, N);
    gather1_kernel<<<(N + 7) / 8, 256>>>(N);

    // layer 2
    gemm2_kernel<<<(N + 63) / 64, 256>>>(W2, b1, N);
    gather2_kernel<<<(N + 7) / 8, 256>>>(b2, out, N);
}